// round 3
// baseline (speedup 1.0000x reference)
#include <cuda_runtime.h>

#define BATCH   64
#define D_IN    512
#define D_OUT   512
#define GRID_N  100
#define LN_EPS   1e-5f
#define GRID_EPS 1e-6f

#define OBLK     128                 // o's per CTA
#define NOBLK    (D_OUT / OBLK)      // 4
#define ICHUNK   4                   // i's per CTA
#define NCHUNKS  (D_IN / ICHUNK)     // 128

#define ISTRIDE  (D_OUT * GRID_N * 4)   // 204800 floats per i
#define OSTRIDE  (GRID_N * 4)           // 400 floats per o

// ---- scratch (__device__ globals; no allocations allowed) ----
__device__ int        g_idx_s[BATCH * D_IN];
__device__ float4     g_w_s[BATCH * D_IN];
__device__ ulonglong2 g_ug[D_IN * BATCH];   // per i: up to 64 {mask, gcell}
__device__ int        g_ug_cnt[D_IN];
__device__ float      g_partial[NCHUNKS * BATCH * D_OUT];   // 16.8 MB

// ---------------------------------------------------------------------------
// Kernel 1: LayerNorm + grid index + Bernstein basis weights.
// One CTA per batch, 128 threads, float4 per thread, single fused reduction.
// ---------------------------------------------------------------------------
__global__ __launch_bounds__(128) void prep_kernel(
    const float* __restrict__ x,
    const float* __restrict__ ln_w,
    const float* __restrict__ ln_b,
    const float* __restrict__ M)
{
    const int b = blockIdx.x;
    const int t = threadIdx.x;

    __shared__ float red1[4], red2[4];
    __shared__ float sM[16];
    if (t < 16) sM[t] = M[t];

    const float4 v = reinterpret_cast<const float4*>(x + b * D_IN)[t];

    float s1 = v.x + v.y + v.z + v.w;
    float s2 = v.x * v.x + v.y * v.y + v.z * v.z + v.w * v.w;
    #pragma unroll
    for (int off = 16; off > 0; off >>= 1) {
        s1 += __shfl_xor_sync(0xffffffffu, s1, off);
        s2 += __shfl_xor_sync(0xffffffffu, s2, off);
    }
    if ((t & 31) == 0) { red1[t >> 5] = s1; red2[t >> 5] = s2; }
    __syncthreads();
    if (t < 32) {
        float r1 = (t < 4) ? red1[t] : 0.0f;
        float r2 = (t < 4) ? red2[t] : 0.0f;
        #pragma unroll
        for (int off = 2; off > 0; off >>= 1) {
            r1 += __shfl_xor_sync(0xffffffffu, r1, off);
            r2 += __shfl_xor_sync(0xffffffffu, r2, off);
        }
        if (t == 0) { red1[0] = r1; red2[0] = r2; }
    }
    __syncthreads();

    const float mean = red1[0] * (1.0f / D_IN);
    const float var  = red2[0] * (1.0f / D_IN) - mean * mean;
    const float rstd = rsqrtf(var + LN_EPS);

    const float4 lw = reinterpret_cast<const float4*>(ln_w)[t];
    const float4 lb = reinterpret_cast<const float4*>(ln_b)[t];

    const float vv[4] = { v.x, v.y, v.z, v.w };
    const float ww[4] = { lw.x, lw.y, lw.z, lw.w };
    const float bb[4] = { lb.x, lb.y, lb.z, lb.w };

    #pragma unroll
    for (int j = 0; j < 4; j++) {
        const int i = t * 4 + j;
        float xn = (vv[j] - mean) * rstd * ww[j] + bb[j];
        xn = fminf(fmaxf(xn, -1.0f + GRID_EPS), 1.0f - GRID_EPS);
        xn = (xn + 1.0f) * 0.5f;
        const float scaled = xn * (float)GRID_N;
        int gi = (int)floorf(scaled);
        gi = max(0, min(gi, GRID_N - 1));
        const float tt  = scaled - (float)gi;
        const float tt2 = tt * tt;
        const float tt3 = tt2 * tt;

        float4 w;
        w.x = sM[0] + tt * sM[4] + tt2 * sM[8]  + tt3 * sM[12];
        w.y = sM[1] + tt * sM[5] + tt2 * sM[9]  + tt3 * sM[13];
        w.z = sM[2] + tt * sM[6] + tt2 * sM[10] + tt3 * sM[14];
        w.w = sM[3] + tt * sM[7] + tt2 * sM[11] + tt3 * sM[15];

        g_idx_s[b * D_IN + i] = gi;
        g_w_s  [b * D_IN + i] = w;
    }
}

// ---------------------------------------------------------------------------
// Kernel 2: per-i unique grid cells + batch masks (deterministic order).
// One CTA per i, 64 threads (one per batch).
// ---------------------------------------------------------------------------
__global__ __launch_bounds__(64) void build_unique_kernel()
{
    const int i = blockIdx.x;
    const int b = threadIdx.x;

    __shared__ unsigned long long cm[GRID_N];
    for (int c = b; c < GRID_N; c += 64) cm[c] = 0ull;
    __syncthreads();

    const int g = g_idx_s[b * D_IN + i];
    atomicOr(&cm[g], 1ull << b);
    __syncthreads();

    if (b == 0) {
        int cnt = 0;
        ulonglong2* dst = &g_ug[i * BATCH];
        #pragma unroll 4
        for (int c = 0; c < GRID_N; c++) {
            const unsigned long long m = cm[c];
            if (m) {
                ulonglong2 e; e.x = m; e.y = (unsigned long long)c;
                dst[cnt++] = e;
            }
        }
        g_ug_cnt[i] = cnt;
    }
}

// ---------------------------------------------------------------------------
// Kernel 3: deduplicated gather. One float4 load per unique (i,g) per o,
// scattered into a shared-memory per-batch accumulator via the batch mask.
// grid = (NOBLK=4, NCHUNKS=128), 128 threads (one per o in block).
// ---------------------------------------------------------------------------
__global__ __launch_bounds__(128) void gather_kernel(const float* __restrict__ poly)
{
    const int tid   = threadIdx.x;
    const int o     = blockIdx.x * OBLK + tid;
    const int chunk = blockIdx.y;
    const int i0    = chunk * ICHUNK;

    __shared__ float  acc_s[BATCH][OBLK];   // 32 KB
    __shared__ float4 w_s[ICHUNK][BATCH];   // 4 KB

    #pragma unroll
    for (int b = 0; b < BATCH; b++) acc_s[b][tid] = 0.0f;

    #pragma unroll
    for (int t = tid; t < ICHUNK * BATCH; t += OBLK) {
        const int ii = t >> 6;       // t / 64
        const int b  = t & 63;       // t % 64
        w_s[ii][b] = g_w_s[b * D_IN + i0 + ii];
    }
    __syncthreads();

    #pragma unroll
    for (int ii = 0; ii < ICHUNK; ii++) {
        const int i   = i0 + ii;
        const int cnt = g_ug_cnt[i];
        const float* pb = poly + (size_t)i * ISTRIDE + (size_t)o * OSTRIDE;
        const ulonglong2* ug = &g_ug[i * BATCH];

        // software pipeline: prefetch next unique-g load
        ulonglong2 e = ug[0];
        float4 pv = __ldcs(reinterpret_cast<const float4*>(pb + (int)e.y * 4));

        for (int j = 0; j < cnt; j++) {
            const float4 cur = pv;
            unsigned long long m = e.x;
            if (j + 1 < cnt) {
                e = ug[j + 1];
                pv = __ldcs(reinterpret_cast<const float4*>(pb + (int)e.y * 4));
            }
            // m is warp-uniform: no divergence
            while (m) {
                const int b = __ffsll((long long)m) - 1;
                m &= m - 1;
                const float4 w = w_s[ii][b];   // broadcast, conflict-free
                acc_s[b][tid] += w.x * cur.x + w.y * cur.y
                               + w.z * cur.z + w.w * cur.w;
            }
        }
    }

    float* pp = g_partial + ((size_t)chunk * BATCH) * D_OUT + o;
    #pragma unroll
    for (int b = 0; b < BATCH; b++) pp[(size_t)b * D_OUT] = acc_s[b][tid];
}

// ---------------------------------------------------------------------------
// Kernel 4: reduce partials over chunks (deterministic).
// ---------------------------------------------------------------------------
__global__ __launch_bounds__(256) void reduce_kernel(float* __restrict__ out)
{
    const int idx = blockIdx.x * blockDim.x + threadIdx.x;   // b*512 + o
    float acc = 0.0f;
    #pragma unroll 8
    for (int c = 0; c < NCHUNKS; c++)
        acc += g_partial[(size_t)c * (BATCH * D_OUT) + idx];
    out[idx] = acc;
}

// ---------------------------------------------------------------------------
extern "C" void kernel_launch(void* const* d_in, const int* in_sizes, int n_in,
                              void* d_out, int out_size)
{
    const float* x    = (const float*)d_in[0];   // (64, 512)
    const float* poly = (const float*)d_in[1];   // (512, 512, 100, 4)
    const float* ln_w = (const float*)d_in[2];   // (512,)
    const float* ln_b = (const float*)d_in[3];   // (512,)
    const float* M    = (const float*)d_in[4];   // (4, 4)
    float* out = (float*)d_out;                  // (64, 512) fp32

    prep_kernel<<<BATCH, 128>>>(x, ln_w, ln_b, M);
    build_unique_kernel<<<D_IN, 64>>>();
    gather_kernel<<<dim3(NOBLK, NCHUNKS), OBLK>>>(poly);
    reduce_kernel<<<(BATCH * D_OUT) / 256, 256>>>(out);
}

// round 4
// speedup vs baseline: 2.0854x; 2.0854x over previous
#include <cuda_runtime.h>

#define BATCH   64
#define D_IN    512
#define D_OUT   512
#define GRID_N  100
#define LN_EPS   1e-5f
#define GRID_EPS 1e-6f

#define OBLK     128                 // o's per CTA
#define NOBLK    (D_OUT / OBLK)      // 4
#define ICHUNK   4                   // i's per CTA
#define NCHUNKS  (D_IN / ICHUNK)     // 128

#define ISTRIDE  (D_OUT * GRID_N * 4)   // 204800 floats per i
#define OSTRIDE  (GRID_N * 4)           // 400 floats per o

// ---- scratch (__device__ globals; no allocations allowed) ----
__device__ int        g_idx_s[BATCH * D_IN];
__device__ float4     g_w_s[BATCH * D_IN];
__device__ ulonglong2 g_ug[D_IN * BATCH];   // per i: up to 64 {mask, gcell}
__device__ int        g_ug_cnt[D_IN];
__device__ float      g_partial[NCHUNKS * BATCH * D_OUT];   // 16.8 MB

// ---------------------------------------------------------------------------
// Kernel 1: LayerNorm + grid index + Bernstein basis weights.
// ---------------------------------------------------------------------------
__global__ __launch_bounds__(128) void prep_kernel(
    const float* __restrict__ x,
    const float* __restrict__ ln_w,
    const float* __restrict__ ln_b,
    const float* __restrict__ M)
{
    const int b = blockIdx.x;
    const int t = threadIdx.x;

    __shared__ float red1[4], red2[4];
    __shared__ float sM[16];
    if (t < 16) sM[t] = M[t];

    const float4 v = reinterpret_cast<const float4*>(x + b * D_IN)[t];

    float s1 = v.x + v.y + v.z + v.w;
    float s2 = v.x * v.x + v.y * v.y + v.z * v.z + v.w * v.w;
    #pragma unroll
    for (int off = 16; off > 0; off >>= 1) {
        s1 += __shfl_xor_sync(0xffffffffu, s1, off);
        s2 += __shfl_xor_sync(0xffffffffu, s2, off);
    }
    if ((t & 31) == 0) { red1[t >> 5] = s1; red2[t >> 5] = s2; }
    __syncthreads();
    if (t < 32) {
        float r1 = (t < 4) ? red1[t] : 0.0f;
        float r2 = (t < 4) ? red2[t] : 0.0f;
        #pragma unroll
        for (int off = 2; off > 0; off >>= 1) {
            r1 += __shfl_xor_sync(0xffffffffu, r1, off);
            r2 += __shfl_xor_sync(0xffffffffu, r2, off);
        }
        if (t == 0) { red1[0] = r1; red2[0] = r2; }
    }
    __syncthreads();

    const float mean = red1[0] * (1.0f / D_IN);
    const float var  = red2[0] * (1.0f / D_IN) - mean * mean;
    const float rstd = rsqrtf(var + LN_EPS);

    const float4 lw = reinterpret_cast<const float4*>(ln_w)[t];
    const float4 lb = reinterpret_cast<const float4*>(ln_b)[t];

    const float vv[4] = { v.x, v.y, v.z, v.w };
    const float ww[4] = { lw.x, lw.y, lw.z, lw.w };
    const float bb[4] = { lb.x, lb.y, lb.z, lb.w };

    #pragma unroll
    for (int j = 0; j < 4; j++) {
        const int i = t * 4 + j;
        float xn = (vv[j] - mean) * rstd * ww[j] + bb[j];
        xn = fminf(fmaxf(xn, -1.0f + GRID_EPS), 1.0f - GRID_EPS);
        xn = (xn + 1.0f) * 0.5f;
        const float scaled = xn * (float)GRID_N;
        int gi = (int)floorf(scaled);
        gi = max(0, min(gi, GRID_N - 1));
        const float tt  = scaled - (float)gi;
        const float tt2 = tt * tt;
        const float tt3 = tt2 * tt;

        float4 w;
        w.x = sM[0] + tt * sM[4] + tt2 * sM[8]  + tt3 * sM[12];
        w.y = sM[1] + tt * sM[5] + tt2 * sM[9]  + tt3 * sM[13];
        w.z = sM[2] + tt * sM[6] + tt2 * sM[10] + tt3 * sM[14];
        w.w = sM[3] + tt * sM[7] + tt2 * sM[11] + tt3 * sM[15];

        g_idx_s[b * D_IN + i] = gi;
        g_w_s  [b * D_IN + i] = w;
    }
}

// ---------------------------------------------------------------------------
// Kernel 2: per-i unique grid cells + batch masks (deterministic order).
// ---------------------------------------------------------------------------
__global__ __launch_bounds__(64) void build_unique_kernel()
{
    const int i = blockIdx.x;
    const int b = threadIdx.x;

    __shared__ unsigned long long cm[GRID_N];
    for (int c = b; c < GRID_N; c += 64) cm[c] = 0ull;
    __syncthreads();

    const int g = g_idx_s[b * D_IN + i];
    atomicOr(&cm[g], 1ull << b);
    __syncthreads();

    if (b == 0) {
        int cnt = 0;
        ulonglong2* dst = &g_ug[i * BATCH];
        #pragma unroll 4
        for (int c = 0; c < GRID_N; c++) {
            const unsigned long long m = cm[c];
            if (m) {
                ulonglong2 e; e.x = m; e.y = (unsigned long long)c;
                dst[cnt++] = e;
            }
        }
        g_ug_cnt[i] = cnt;
    }
}

// ---------------------------------------------------------------------------
// Kernel 3: deduplicated gather with wave-of-8 pipelined loads (MLP=8).
// grid = (NOBLK=4, NCHUNKS=128), 128 threads (one per o in block).
// ---------------------------------------------------------------------------
#define WAVE 8

__global__ __launch_bounds__(128) void gather_kernel(const float* __restrict__ poly)
{
    const int tid   = threadIdx.x;
    const int o     = blockIdx.x * OBLK + tid;
    const int chunk = blockIdx.y;
    const int i0    = chunk * ICHUNK;

    __shared__ float  acc_s[BATCH][OBLK];   // 32 KB
    __shared__ float4 w_s[ICHUNK][BATCH];   // 4 KB

    #pragma unroll
    for (int b = 0; b < BATCH; b++) acc_s[b][tid] = 0.0f;

    #pragma unroll
    for (int t = tid; t < ICHUNK * BATCH; t += OBLK) {
        const int ii = t >> 6;       // t / 64
        const int b  = t & 63;       // t % 64
        w_s[ii][b] = g_w_s[b * D_IN + i0 + ii];
    }
    __syncthreads();

    #pragma unroll
    for (int ii = 0; ii < ICHUNK; ii++) {
        const int i   = i0 + ii;
        const int cnt = g_ug_cnt[i];
        const float* pb = poly + (size_t)i * ISTRIDE + (size_t)o * OSTRIDE;
        const ulonglong2* ug = &g_ug[i * BATCH];

        for (int j0 = 0; j0 < cnt; j0 += WAVE) {
            const int n = min(WAVE, cnt - j0);

            // ---- load wave: up to 8 independent gathers in flight ----
            float4             pv[WAVE];
            unsigned long long mk[WAVE];
            #pragma unroll
            for (int jj = 0; jj < WAVE; jj++) {
                if (jj < n) {
                    const ulonglong2 e = ug[j0 + jj];
                    mk[jj] = e.x;
                    pv[jj] = __ldcs(reinterpret_cast<const float4*>(
                                 pb + (int)e.y * 4));
                }
            }

            // ---- scatter wave (mask is warp-uniform: no divergence) ----
            #pragma unroll
            for (int jj = 0; jj < WAVE; jj++) {
                if (jj < n) {
                    unsigned long long m = mk[jj];
                    const float4 cur = pv[jj];
                    while (m) {
                        const int b = __ffsll((long long)m) - 1;
                        m &= m - 1;
                        const float4 w = w_s[ii][b];
                        acc_s[b][tid] += w.x * cur.x + w.y * cur.y
                                       + w.z * cur.z + w.w * cur.w;
                    }
                }
            }
        }
    }

    float* pp = g_partial + ((size_t)chunk * BATCH) * D_OUT + o;
    #pragma unroll
    for (int b = 0; b < BATCH; b++) pp[(size_t)b * D_OUT] = acc_s[b][tid];
}

// ---------------------------------------------------------------------------
// Kernel 4: reduce partials over chunks (float4 vectorized, deterministic).
// 8192 threads, each reduces 4 consecutive outputs over 128 chunks.
// ---------------------------------------------------------------------------
__global__ __launch_bounds__(256) void reduce_kernel(float* __restrict__ out)
{
    const int idx4 = blockIdx.x * blockDim.x + threadIdx.x;   // float4 index
    const float4* p = reinterpret_cast<const float4*>(g_partial) + idx4;

    float4 acc = make_float4(0.f, 0.f, 0.f, 0.f);
    #pragma unroll 8
    for (int c = 0; c < NCHUNKS; c++) {
        const float4 v = p[(size_t)c * (BATCH * D_OUT / 4)];
        acc.x += v.x; acc.y += v.y; acc.z += v.z; acc.w += v.w;
    }
    reinterpret_cast<float4*>(out)[idx4] = acc;
}

// ---------------------------------------------------------------------------
extern "C" void kernel_launch(void* const* d_in, const int* in_sizes, int n_in,
                              void* d_out, int out_size)
{
    const float* x    = (const float*)d_in[0];   // (64, 512)
    const float* poly = (const float*)d_in[1];   // (512, 512, 100, 4)
    const float* ln_w = (const float*)d_in[2];   // (512,)
    const float* ln_b = (const float*)d_in[3];   // (512,)
    const float* M    = (const float*)d_in[4];   // (4, 4)
    float* out = (float*)d_out;                  // (64, 512) fp32

    prep_kernel<<<BATCH, 128>>>(x, ln_w, ln_b, M);
    build_unique_kernel<<<D_IN, 64>>>();
    gather_kernel<<<dim3(NOBLK, NCHUNKS), OBLK>>>(poly);
    reduce_kernel<<<(BATCH * D_OUT / 4) / 256, 256>>>(out);
}